// round 1
// baseline (speedup 1.0000x reference)
#include <cuda_runtime.h>

#define NB   64
#define NC   256
#define NL   4096
#define NOUT 256
#define NTOK (NB * NL)   // 262144 tokens

// ---------------- scratch (device globals; no allocation allowed) ----------------
__device__ float g_xt  [(long long)NTOK * NC];  // x transposed: [b][l][c]
__device__ float g_q   [(long long)NTOK * NC];  // q token-major
__device__ float g_k   [(long long)NTOK * NC];
__device__ float g_v   [(long long)NTOK * NC];
__device__ float g_virt[(long long)NTOK * NC];
__device__ float g_yt  [(long long)NTOK * NC];  // y = x + conv2(...) token-major
__device__ float g_psum[NB];
__device__ float g_psumsq[NB];
__device__ float g_mean[NB];
__device__ float g_rstd[NB];

// ---------------- K0: zero GroupNorm accumulators ----------------
__global__ void k_zero()
{
    int t = threadIdx.x;
    if (t < NB) { g_psum[t] = 0.f; g_psumsq[t] = 0.f; }
}

// ---------------- K1: fused QKV 1x1 conv + x transpose ----------------
// out[t][o] = sum_c W[o][c] * x[b][c][l],  t = b*NL + l, o in [0,768)
// grid: (2048 t-tiles of 128, 6 o-tiles of 128); threads 256 (16x16), 8x8 per thread.
__global__ __launch_bounds__(256) void k_qkv(
    const float* __restrict__ x,
    const float* __restrict__ Wq,
    const float* __restrict__ Wk,
    const float* __restrict__ Wv)
{
    __shared__ float As[16][132];   // [k][t]
    __shared__ float Ws[16][132];   // [k][o]

    const int tt = blockIdx.x;
    const int by = blockIdx.y;
    const int b  = tt >> 5;              // 32 l-tiles per batch (4096/128)
    const int l0 = (tt & 31) << 7;
    const int t0 = b * NL + l0;
    const int tensor = by >> 1;          // 0:q 1:k 2:v
    const int o0 = (by & 1) << 7;
    const float* W = (tensor == 0) ? Wq : (tensor == 1) ? Wk : Wv;
    float* outp    = (tensor == 0) ? g_q : (tensor == 1) ? g_k : g_v;

    const int tid = threadIdx.x;
    const int tx = tid & 15, ty = tid >> 4;

    float acc[8][8];
#pragma unroll
    for (int i = 0; i < 8; i++)
#pragma unroll
        for (int j = 0; j < 8; j++) acc[i][j] = 0.f;

    const float* xb = x + (size_t)b * NC * NL + l0;

    for (int k0 = 0; k0 < NC; k0 += 16) {
        // A tile: x[b][k0+c][l0+t], coalesced along l
#pragma unroll
        for (int r = 0; r < 2; r++) {
            int idx = tid + r * 256;
            int c = idx >> 5, t4 = (idx & 31) << 2;
            *(float4*)&As[c][t4] = *(const float4*)(xb + (size_t)(k0 + c) * NL + t4);
        }
        // W tile: W[o0+o][k0+c], scatter-transposed into [k][o]
#pragma unroll
        for (int r = 0; r < 2; r++) {
            int idx = tid + r * 256;
            int o = idx >> 2, c4 = (idx & 3) << 2;
            float4 w = *(const float4*)(W + (size_t)(o0 + o) * NC + k0 + c4);
            Ws[c4 + 0][o] = w.x; Ws[c4 + 1][o] = w.y;
            Ws[c4 + 2][o] = w.z; Ws[c4 + 3][o] = w.w;
        }
        __syncthreads();

        // transpose x -> x_t (only o-tile 0 does it; covers all c over the k-loop)
        if (by == 0) {
#pragma unroll
            for (int r = 0; r < 2; r++) {
                int idx = tid + r * 256;
                int ll = idx >> 2, c4 = (idx & 3) << 2;
                float4 v = make_float4(As[c4][ll], As[c4 + 1][ll], As[c4 + 2][ll], As[c4 + 3][ll]);
                *(float4*)(g_xt + (size_t)(t0 + ll) * NC + k0 + c4) = v;
            }
        }

        float af[8], bf[8];
#pragma unroll
        for (int kk = 0; kk < 16; kk++) {
            *(float4*)&af[0] = *(float4*)&As[kk][ty * 8];
            *(float4*)&af[4] = *(float4*)&As[kk][ty * 8 + 4];
            *(float4*)&bf[0] = *(float4*)&Ws[kk][tx * 8];
            *(float4*)&bf[4] = *(float4*)&Ws[kk][tx * 8 + 4];
#pragma unroll
            for (int i = 0; i < 8; i++)
#pragma unroll
                for (int j = 0; j < 8; j++)
                    acc[i][j] = fmaf(af[i], bf[j], acc[i][j]);
        }
        __syncthreads();
    }

#pragma unroll
    for (int i = 0; i < 8; i++) {
        float* op = outp + (size_t)(t0 + ty * 8 + i) * NC + o0 + tx * 8;
        *(float4*)(op)     = make_float4(acc[i][0], acc[i][1], acc[i][2], acc[i][3]);
        *(float4*)(op + 4) = make_float4(acc[i][4], acc[i][5], acc[i][6], acc[i][7]);
    }
}

// ---------------- K2: per-l batch attention + GroupNorm partial sums ----------------
#define QS_STR 260
#define KT_STR 65
#define AT_STR 66
#define SM_ATTN_FLOATS (64 * QS_STR + 256 * KT_STR + 64 * 256 + 64 * AT_STR)
#define SM_ATTN_BYTES  (SM_ATTN_FLOATS * 4)

__global__ __launch_bounds__(256) void k_attn()
{
    extern __shared__ float sm[];
    float* Qs  = sm;                       // [b][c] row-major, stride 260
    float* KsT = Qs + 64 * QS_STR;         // [c][d], stride 65
    float* Vs  = KsT + 256 * KT_STR;       // [d][c] row-major, stride 256
    float* att = Vs + 64 * 256;            // [b][d], stride 66

    const int l = blockIdx.x;
    const int tid = threadIdx.x;

    // load Q,K,V for this l (rows are 1KB contiguous in token-major layout)
    for (int idx = tid; idx < 64 * 64; idx += 256) {
        int row = idx >> 6;
        int c4  = (idx & 63) << 2;
        size_t g = ((size_t)row * NL + l) * NC + c4;
        float4 q = *(const float4*)(g_q + g);
        *(float4*)&Qs[row * QS_STR + c4] = q;
        float4 k = *(const float4*)(g_k + g);
        KsT[(c4 + 0) * KT_STR + row] = k.x;
        KsT[(c4 + 1) * KT_STR + row] = k.y;
        KsT[(c4 + 2) * KT_STR + row] = k.z;
        KsT[(c4 + 3) * KT_STR + row] = k.w;
        float4 v = *(const float4*)(g_v + g);
        *(float4*)&Vs[row * 256 + c4] = v;
    }
    __syncthreads();

    // scores: att[b][d] = q[b,:]·k[d,:] / 16 ; 16x16 threads, 4x4 each
    const int tx = tid & 15, ty = tid >> 4;
    float acc[4][4];
#pragma unroll
    for (int i = 0; i < 4; i++)
#pragma unroll
        for (int j = 0; j < 4; j++) acc[i][j] = 0.f;

#pragma unroll 4
    for (int c = 0; c < NC; c++) {
        float a0 = Qs[(ty     ) * QS_STR + c];
        float a1 = Qs[(ty + 16) * QS_STR + c];
        float a2 = Qs[(ty + 32) * QS_STR + c];
        float a3 = Qs[(ty + 48) * QS_STR + c];
        const float* kc = KsT + c * KT_STR + tx;
        float b0 = kc[0], b1 = kc[16], b2 = kc[32], b3 = kc[48];
        acc[0][0] = fmaf(a0, b0, acc[0][0]); acc[0][1] = fmaf(a0, b1, acc[0][1]);
        acc[0][2] = fmaf(a0, b2, acc[0][2]); acc[0][3] = fmaf(a0, b3, acc[0][3]);
        acc[1][0] = fmaf(a1, b0, acc[1][0]); acc[1][1] = fmaf(a1, b1, acc[1][1]);
        acc[1][2] = fmaf(a1, b2, acc[1][2]); acc[1][3] = fmaf(a1, b3, acc[1][3]);
        acc[2][0] = fmaf(a2, b0, acc[2][0]); acc[2][1] = fmaf(a2, b1, acc[2][1]);
        acc[2][2] = fmaf(a2, b2, acc[2][2]); acc[2][3] = fmaf(a2, b3, acc[2][3]);
        acc[3][0] = fmaf(a3, b0, acc[3][0]); acc[3][1] = fmaf(a3, b1, acc[3][1]);
        acc[3][2] = fmaf(a3, b2, acc[3][2]); acc[3][3] = fmaf(a3, b3, acc[3][3]);
    }
#pragma unroll
    for (int i = 0; i < 4; i++)
#pragma unroll
        for (int j = 0; j < 4; j++)
            att[(ty + i * 16) * AT_STR + tx + j * 16] = acc[i][j] * 0.0625f;
    __syncthreads();

    // softmax over d (one thread per b-row)
    if (tid < 64) {
        float* row = att + tid * AT_STR;
        float m = row[0];
        for (int d = 1; d < 64; d++) m = fmaxf(m, row[d]);
        float s = 0.f;
        for (int d = 0; d < 64; d++) { float e = __expf(row[d] - m); row[d] = e; s += e; }
        float inv = 1.f / s;
        for (int d = 0; d < 64; d++) row[d] *= inv;
    }
    __syncthreads();

    // virt[b][c] = sum_d att[b][d] * v[d][c] ; thread: fixed b = tid/4, 64 c's
    const int bb = tid >> 2;
    const int q4 = (tid & 3) << 2;
    float4 a4[16];
#pragma unroll
    for (int i = 0; i < 16; i++) a4[i] = make_float4(0.f, 0.f, 0.f, 0.f);

    for (int d = 0; d < 64; d++) {
        float w = att[bb * AT_STR + d];
        const float* vr = Vs + d * 256 + q4;
#pragma unroll
        for (int i = 0; i < 16; i++) {
            float4 v = *(const float4*)(vr + i * 16);
            a4[i].x = fmaf(w, v.x, a4[i].x);
            a4[i].y = fmaf(w, v.y, a4[i].y);
            a4[i].z = fmaf(w, v.z, a4[i].z);
            a4[i].w = fmaf(w, v.w, a4[i].w);
        }
    }

    float s = 0.f, ss = 0.f;
    float* vp = g_virt + ((size_t)bb * NL + l) * NC + q4;
#pragma unroll
    for (int i = 0; i < 16; i++) {
        *(float4*)(vp + i * 16) = a4[i];
        s  += a4[i].x + a4[i].y + a4[i].z + a4[i].w;
        ss += a4[i].x * a4[i].x + a4[i].y * a4[i].y + a4[i].z * a4[i].z + a4[i].w * a4[i].w;
    }
    s  += __shfl_xor_sync(0xffffffffu, s, 1);
    s  += __shfl_xor_sync(0xffffffffu, s, 2);
    ss += __shfl_xor_sync(0xffffffffu, ss, 1);
    ss += __shfl_xor_sync(0xffffffffu, ss, 2);
    if ((tid & 3) == 0) {
        atomicAdd(&g_psum[bb], s);
        atomicAdd(&g_psumsq[bb], ss);
    }
}

// ---------------- K3: per-b mean / rstd ----------------
__global__ void k_stats()
{
    int b = threadIdx.x;
    if (b < NB) {
        const float n = (float)NC * (float)NL;
        float mean = g_psum[b] / n;
        float var  = g_psumsq[b] / n - mean * mean;
        if (var < 0.f) var = 0.f;
        g_mean[b] = mean;
        g_rstd[b] = rsqrtf(var + 1e-5f);
    }
}

// ---------------- K4: GN+ReLU fused into A-load, conv Wc, +x residual ----------------
__global__ __launch_bounds__(256) void k_conv2(
    const float* __restrict__ Wc,
    const float* __restrict__ gamma,
    const float* __restrict__ beta)
{
    __shared__ float As[16][132];
    __shared__ float Ws[16][132];

    const int tt = blockIdx.x, by = blockIdx.y;
    const int b  = tt >> 5;
    const int l0 = (tt & 31) << 7;
    const int t0 = b * NL + l0;
    const int o0 = by << 7;
    const float mean = g_mean[b];
    const float rstd = g_rstd[b];

    const int tid = threadIdx.x;
    const int tx = tid & 15, ty = tid >> 4;

    float acc[8][8];
#pragma unroll
    for (int i = 0; i < 8; i++)
#pragma unroll
        for (int j = 0; j < 8; j++) acc[i][j] = 0.f;

    for (int k0 = 0; k0 < NC; k0 += 16) {
#pragma unroll
        for (int r = 0; r < 2; r++) {
            int idx = tid + r * 256;
            int t = idx >> 2, c4 = (idx & 3) << 2;
            float4 v = *(const float4*)(g_virt + (size_t)(t0 + t) * NC + k0 + c4);
            float g0 = gamma[k0 + c4 + 0], g1 = gamma[k0 + c4 + 1];
            float g2 = gamma[k0 + c4 + 2], g3 = gamma[k0 + c4 + 3];
            float e0 = beta [k0 + c4 + 0], e1 = beta [k0 + c4 + 1];
            float e2 = beta [k0 + c4 + 2], e3 = beta [k0 + c4 + 3];
            v.x = fmaxf(fmaf((v.x - mean) * rstd, g0, e0), 0.f);
            v.y = fmaxf(fmaf((v.y - mean) * rstd, g1, e1), 0.f);
            v.z = fmaxf(fmaf((v.z - mean) * rstd, g2, e2), 0.f);
            v.w = fmaxf(fmaf((v.w - mean) * rstd, g3, e3), 0.f);
            As[c4 + 0][t] = v.x; As[c4 + 1][t] = v.y;
            As[c4 + 2][t] = v.z; As[c4 + 3][t] = v.w;
        }
#pragma unroll
        for (int r = 0; r < 2; r++) {
            int idx = tid + r * 256;
            int o = idx >> 2, c4 = (idx & 3) << 2;
            float4 w = *(const float4*)(Wc + (size_t)(o0 + o) * NC + k0 + c4);
            Ws[c4 + 0][o] = w.x; Ws[c4 + 1][o] = w.y;
            Ws[c4 + 2][o] = w.z; Ws[c4 + 3][o] = w.w;
        }
        __syncthreads();

        float af[8], bf[8];
#pragma unroll
        for (int kk = 0; kk < 16; kk++) {
            *(float4*)&af[0] = *(float4*)&As[kk][ty * 8];
            *(float4*)&af[4] = *(float4*)&As[kk][ty * 8 + 4];
            *(float4*)&bf[0] = *(float4*)&Ws[kk][tx * 8];
            *(float4*)&bf[4] = *(float4*)&Ws[kk][tx * 8 + 4];
#pragma unroll
            for (int i = 0; i < 8; i++)
#pragma unroll
                for (int j = 0; j < 8; j++)
                    acc[i][j] = fmaf(af[i], bf[j], acc[i][j]);
        }
        __syncthreads();
    }

#pragma unroll
    for (int i = 0; i < 8; i++) {
        size_t base = (size_t)(t0 + ty * 8 + i) * NC + o0 + tx * 8;
        float4 x0 = *(const float4*)(g_xt + base);
        float4 x1 = *(const float4*)(g_xt + base + 4);
        *(float4*)(g_yt + base) =
            make_float4(acc[i][0] + x0.x, acc[i][1] + x0.y, acc[i][2] + x0.z, acc[i][3] + x0.w);
        *(float4*)(g_yt + base + 4) =
            make_float4(acc[i][4] + x1.x, acc[i][5] + x1.y, acc[i][6] + x1.z, acc[i][7] + x1.w);
    }
}

// ---------------- K5: output conv, writes (B, OUT, L) with l-coalesced stores ----------------
__global__ __launch_bounds__(256) void k_out(
    const float* __restrict__ Wout, float* __restrict__ out)
{
    __shared__ float As[16][132];   // [k][t]
    __shared__ float Ws[16][132];   // [k][o]

    const int tt = blockIdx.x, by = blockIdx.y;
    const int b  = tt >> 5;
    const int l0 = (tt & 31) << 7;
    const int t0 = b * NL + l0;
    const int o0 = by << 7;

    const int tid = threadIdx.x;
    const int tx = tid & 15, ty = tid >> 4;

    float acc[8][8];   // i -> o, j -> l
#pragma unroll
    for (int i = 0; i < 8; i++)
#pragma unroll
        for (int j = 0; j < 8; j++) acc[i][j] = 0.f;

    for (int k0 = 0; k0 < NC; k0 += 16) {
#pragma unroll
        for (int r = 0; r < 2; r++) {
            int idx = tid + r * 256;
            int t = idx >> 2, c4 = (idx & 3) << 2;
            float4 v = *(const float4*)(g_yt + (size_t)(t0 + t) * NC + k0 + c4);
            As[c4 + 0][t] = v.x; As[c4 + 1][t] = v.y;
            As[c4 + 2][t] = v.z; As[c4 + 3][t] = v.w;
        }
#pragma unroll
        for (int r = 0; r < 2; r++) {
            int idx = tid + r * 256;
            int o = idx >> 2, c4 = (idx & 3) << 2;
            float4 w = *(const float4*)(Wout + (size_t)(o0 + o) * NC + k0 + c4);
            Ws[c4 + 0][o] = w.x; Ws[c4 + 1][o] = w.y;
            Ws[c4 + 2][o] = w.z; Ws[c4 + 3][o] = w.w;
        }
        __syncthreads();

        float af[8], bf[8];
#pragma unroll
        for (int kk = 0; kk < 16; kk++) {
            *(float4*)&af[0] = *(float4*)&Ws[kk][ty * 8];       // o
            *(float4*)&af[4] = *(float4*)&Ws[kk][ty * 8 + 4];
            *(float4*)&bf[0] = *(float4*)&As[kk][tx * 8];       // l
            *(float4*)&bf[4] = *(float4*)&As[kk][tx * 8 + 4];
#pragma unroll
            for (int i = 0; i < 8; i++)
#pragma unroll
                for (int j = 0; j < 8; j++)
                    acc[i][j] = fmaf(af[i], bf[j], acc[i][j]);
        }
        __syncthreads();
    }

#pragma unroll
    for (int i = 0; i < 8; i++) {
        float* op = out + (size_t)b * NOUT * NL + (size_t)(o0 + ty * 8 + i) * NL + l0 + tx * 8;
        *(float4*)(op)     = make_float4(acc[i][0], acc[i][1], acc[i][2], acc[i][3]);
        *(float4*)(op + 4) = make_float4(acc[i][4], acc[i][5], acc[i][6], acc[i][7]);
    }
}

// ---------------- launch ----------------
extern "C" void kernel_launch(void* const* d_in, const int* in_sizes, int n_in,
                              void* d_out, int out_size)
{
    const float* x     = (const float*)d_in[0];
    const float* Wq    = (const float*)d_in[1];
    const float* Wk    = (const float*)d_in[2];
    const float* Wv    = (const float*)d_in[3];
    const float* Wc    = (const float*)d_in[4];
    const float* Wout  = (const float*)d_in[5];
    const float* gamma = (const float*)d_in[6];
    const float* beta  = (const float*)d_in[7];
    float* out = (float*)d_out;

    cudaFuncSetAttribute(k_attn, cudaFuncAttributeMaxDynamicSharedMemorySize, SM_ATTN_BYTES);

    k_zero<<<1, 128>>>();
    k_qkv<<<dim3(2048, 6), 256>>>(x, Wq, Wk, Wv);
    k_attn<<<NL, 256, SM_ATTN_BYTES>>>();
    k_stats<<<1, 64>>>();
    k_conv2<<<dim3(2048, 2), 256>>>(Wc, gamma, beta);
    k_out<<<dim3(2048, 2), 256>>>(Wout, out);
}

// round 7
// speedup vs baseline: 1.1717x; 1.1717x over previous
#include <cuda_runtime.h>
#include <cuda_bf16.h>
#include <cstdint>

#define NB   64
#define NC   256
#define NL   4096
#define NOUT 256
#define NTOK (NB * NL)   // 262144 tokens

// ================= helpers =================
__device__ __forceinline__ uint32_t smem_to_u32(const void* p) {
    uint32_t a;
    asm("{ .reg .u64 t; cvta.to.shared.u64 t, %1; cvt.u32.u64 %0, t; }" : "=r"(a) : "l"(p));
    return a;
}
__device__ __forceinline__ void cpa16(uint32_t s, const void* g) {
    asm volatile("cp.async.cg.shared.global [%0], [%1], 16;" :: "r"(s), "l"(g) : "memory");
}
__device__ __forceinline__ uint32_t lds32v(uint32_t a) {
    uint32_t v;
    asm volatile("ld.shared.b32 %0, [%1];" : "=r"(v) : "r"(a) : "memory");
    return v;
}
#define MMA16816(d, a, b) \
    asm volatile("mma.sync.aligned.m16n8k16.row.col.f32.bf16.bf16.f32 " \
        "{%0,%1,%2,%3},{%4,%5,%6,%7},{%8,%9},{%0,%1,%2,%3};" \
        : "+f"((d)[0]), "+f"((d)[1]), "+f"((d)[2]), "+f"((d)[3]) \
        : "r"((a)[0]), "r"((a)[1]), "r"((a)[2]), "r"((a)[3]), "r"((b)[0]), "r"((b)[1]))

// ================= scratch (device globals; referenced ONLY in device code) =================
__device__ __align__(256) float         g_xt  [(long long)NTOK * NC];
__device__ __align__(256) __nv_bfloat16 g_xh  [(long long)NTOK * NC];
__device__ __align__(256) __nv_bfloat16 g_xl  [(long long)NTOK * NC];
__device__ __align__(256) float         g_z   [(long long)NTOK * NC];
__device__ __align__(256) float         g_v   [(long long)NTOK * NC];
__device__ __align__(256) float         g_virt[(long long)NTOK * NC];
__device__ __align__(256) __nv_bfloat16 g_nh  [(long long)NTOK * NC];
__device__ __align__(256) __nv_bfloat16 g_nl  [(long long)NTOK * NC];
__device__ __align__(256) __nv_bfloat16 g_yh  [(long long)NTOK * NC];
__device__ __align__(256) __nv_bfloat16 g_yl  [(long long)NTOK * NC];
__device__ __align__(256) __nv_bfloat16 g_Gh[NC * NC],  g_Gl[NC * NC];
__device__ __align__(256) __nv_bfloat16 g_wvh[NC * NC], g_wvl[NC * NC];
__device__ __align__(256) __nv_bfloat16 g_wch[NC * NC], g_wcl[NC * NC];
__device__ __align__(256) __nv_bfloat16 g_woh[NC * NC], g_wol[NC * NC];
__device__ float g_psum[NB], g_psumsq[NB], g_mean[NB], g_rstd[NB];

// ================= K: zero GN accumulators =================
__global__ void k_zero()
{
    int t = threadIdx.x;
    if (t < NB) { g_psum[t] = 0.f; g_psumsq[t] = 0.f; }
}

// ================= K: transpose x -> x_t (fp32) + bf16 hi/lo split =================
__global__ __launch_bounds__(256) void k_prep0(const float* __restrict__ x)
{
    __shared__ float tile[64][65];
    const int b  = blockIdx.z;
    const int l0 = blockIdx.x << 6;
    const int c0 = blockIdx.y << 6;
    const int tid = threadIdx.x;
    const int tx = tid & 63, ty = tid >> 6;

    const float* xp = x + (size_t)b * NC * NL + (size_t)c0 * NL + l0;
#pragma unroll
    for (int i = 0; i < 16; i++) {
        int r = i * 4 + ty;
        tile[r][tx] = xp[(size_t)r * NL + tx];
    }
    __syncthreads();
#pragma unroll
    for (int i = 0; i < 16; i++) {
        int lr = i * 4 + ty;
        float v = tile[tx][lr];
        size_t idx = ((size_t)(b * NL + l0 + lr)) * NC + c0 + tx;
        g_xt[idx] = v;
        __nv_bfloat16 h = __float2bfloat16(v);
        g_xh[idx] = h;
        g_xl[idx] = __float2bfloat16(v - __bfloat162float(h));
    }
}

// ================= K: G[e][f] = sum_o Wq[o][e] Wk[o][f], split bf16 hi/lo =================
__global__ __launch_bounds__(256) void k_gmat(const float* __restrict__ Wq, const float* __restrict__ Wk)
{
    __shared__ float sA[16][68], sB[16][68];
    const int e0 = (blockIdx.x & 3) << 6;
    const int f0 = (blockIdx.x >> 2) << 6;
    const int tid = threadIdx.x;
    const int tx = tid & 15, ty = tid >> 4;

    float acc[4][4];
#pragma unroll
    for (int i = 0; i < 4; i++)
#pragma unroll
        for (int j = 0; j < 4; j++) acc[i][j] = 0.f;

    for (int k0 = 0; k0 < NC; k0 += 16) {
#pragma unroll
        for (int i = 0; i < 4; i++) {
            int r = (tid >> 6) + i * 4, col = tid & 63;
            sA[r][col] = Wq[(size_t)(k0 + r) * NC + e0 + col];
            sB[r][col] = Wk[(size_t)(k0 + r) * NC + f0 + col];
        }
        __syncthreads();
#pragma unroll
        for (int kk = 0; kk < 16; kk++) {
            float a[4], bb[4];
#pragma unroll
            for (int i = 0; i < 4; i++) { a[i] = sA[kk][ty * 4 + i]; bb[i] = sB[kk][tx * 4 + i]; }
#pragma unroll
            for (int i = 0; i < 4; i++)
#pragma unroll
                for (int j = 0; j < 4; j++) acc[i][j] = fmaf(a[i], bb[j], acc[i][j]);
        }
        __syncthreads();
    }
#pragma unroll
    for (int i = 0; i < 4; i++)
#pragma unroll
        for (int j = 0; j < 4; j++) {
            int e = e0 + ty * 4 + i, f = f0 + tx * 4 + j;
            float g = acc[i][j];
            __nv_bfloat16 h = __float2bfloat16(g);
            g_Gh[e * NC + f] = h;
            g_Gl[e * NC + f] = __float2bfloat16(g - __bfloat162float(h));
        }
}

// ================= K: split Wv, Wc, Wout to bf16 hi/lo =================
__global__ __launch_bounds__(256) void k_prepw(
    const float* __restrict__ Wv, const float* __restrict__ Wc, const float* __restrict__ Wo)
{
    int gid = blockIdx.x * 256 + threadIdx.x;
    int arr = gid >> 14;
    int off = (gid & 16383) * 4;
    const float* src = (arr == 0) ? Wv : (arr == 1) ? Wc : Wo;
    __nv_bfloat16* dh = (arr == 0) ? g_wvh : (arr == 1) ? g_wch : g_woh;
    __nv_bfloat16* dl = (arr == 0) ? g_wvl : (arr == 1) ? g_wcl : g_wol;
    float4 v = *(const float4*)(src + off);
    float vv[4] = { v.x, v.y, v.z, v.w };
#pragma unroll
    for (int i = 0; i < 4; i++) {
        __nv_bfloat16 h = __float2bfloat16(vv[i]);
        dh[off + i] = h;
        dl[off + i] = __float2bfloat16(vv[i] - __bfloat162float(h));
    }
}

// ================= K: mma.sync bf16-split GEMM (operands selected IN DEVICE CODE) =================
// C[t][o] = sum_c A[t][c] * W[o][c].  CTA tile 128x128, K in 16-wide stages.
// smem row = 80B: [16B hi k0..7 | 16B hi k8..15 | 16B lo k0..7 | 16B lo k8..15 | 16B pad].
// MODE 0: A=x,  W=G    -> g_z
// MODE 1: A=x,  W=Wv   -> g_v
// MODE 2: A=gn, W=Wc   -> y = acc + x_t -> g_yh/g_yl
// MODE 3: A=y,  W=Wout -> outf[b][o][l] (transposed store)
#define ROWB   80
#define HALF_B (128 * ROWB)     // 10240 per operand
#define STAGE_B (2 * HALF_B)    // 20480 per stage

template<int MODE>
__global__ __launch_bounds__(256) void k_gemm(float* __restrict__ outf)
{
    const __nv_bfloat16* __restrict__ Ah;
    const __nv_bfloat16* __restrict__ Al;
    const __nv_bfloat16* __restrict__ Wh;
    const __nv_bfloat16* __restrict__ Wl;
    if      (MODE == 0) { Ah = g_xh; Al = g_xl; Wh = g_Gh;  Wl = g_Gl;  }
    else if (MODE == 1) { Ah = g_xh; Al = g_xl; Wh = g_wvh; Wl = g_wvl; }
    else if (MODE == 2) { Ah = g_nh; Al = g_nl; Wh = g_wch; Wl = g_wcl; }
    else                { Ah = g_yh; Al = g_yl; Wh = g_woh; Wl = g_wol; }

    __shared__ __align__(128) char smem[2 * STAGE_B];   // 40 KB static
    const uint32_t sbase = smem_to_u32(smem);
    const int tid  = threadIdx.x;
    const int wid  = tid >> 5;
    const int lane = tid & 31;
    const int t0   = blockIdx.x << 7;
    const int o0   = blockIdx.y << 7;
    const int wm   = wid & 1;     // 2 warps over M (64 rows each)
    const int wn   = wid >> 1;    // 4 warps over N (32 cols each)

    auto load_stage = [&](int s) {
        const uint32_t buf = sbase + (uint32_t)(s & 1) * STAGE_B;
        const int k0 = s << 4;
#pragma unroll
        for (int i = 0; i < 2; i++) {
            int idx = tid + (i << 8);          // [0,512)
            int r = idx >> 2, ch = idx & 3;
            const __nv_bfloat16* srcA = ((ch < 2) ? Ah : Al) + (size_t)(t0 + r) * NC + k0 + ((ch & 1) << 3);
            cpa16(buf + (uint32_t)(r * ROWB + (ch << 4)), srcA);
            const __nv_bfloat16* srcW = ((ch < 2) ? Wh : Wl) + (size_t)(o0 + r) * NC + k0 + ((ch & 1) << 3);
            cpa16(buf + (uint32_t)HALF_B + (uint32_t)(r * ROWB + (ch << 4)), srcW);
        }
        asm volatile("cp.async.commit_group;" ::: "memory");
    };

    float acc[4][4][4];
#pragma unroll
    for (int a = 0; a < 4; a++)
#pragma unroll
        for (int b = 0; b < 4; b++)
#pragma unroll
            for (int c = 0; c < 4; c++) acc[a][b][c] = 0.f;

    const int rq = lane >> 2;          // 0..7
    const int p4 = (lane & 3) << 2;    // 0,4,8,12 bytes -> k = (lane&3)*2

    load_stage(0);

    for (int s = 0; s < 16; s++) {
        if (s + 1 < 16) {
            load_stage(s + 1);
            asm volatile("cp.async.wait_group 1;" ::: "memory");
        } else {
            asm volatile("cp.async.wait_group 0;" ::: "memory");
        }
        __syncthreads();

        const uint32_t bufA = sbase + (uint32_t)(s & 1) * STAGE_B;
        const uint32_t bufW = bufA + (uint32_t)HALF_B;

        uint32_t ah[4][4], al[4][4], bh[4][2], bl[4][2];
#pragma unroll
        for (int mt = 0; mt < 4; mt++) {
            uint32_t base = bufA + (uint32_t)((wm * 64 + mt * 16 + rq) * ROWB + p4);
            ah[mt][0] = lds32v(base);
            ah[mt][1] = lds32v(base + 8 * ROWB);
            ah[mt][2] = lds32v(base + 16);
            ah[mt][3] = lds32v(base + 8 * ROWB + 16);
            al[mt][0] = lds32v(base + 32);
            al[mt][1] = lds32v(base + 8 * ROWB + 32);
            al[mt][2] = lds32v(base + 48);
            al[mt][3] = lds32v(base + 8 * ROWB + 48);
        }
#pragma unroll
        for (int nt = 0; nt < 4; nt++) {
            uint32_t base = bufW + (uint32_t)((wn * 32 + nt * 8 + rq) * ROWB + p4);
            bh[nt][0] = lds32v(base);
            bh[nt][1] = lds32v(base + 16);
            bl[nt][0] = lds32v(base + 32);
            bl[nt][1] = lds32v(base + 48);
        }
#pragma unroll
        for (int mt = 0; mt < 4; mt++)
#pragma unroll
            for (int nt = 0; nt < 4; nt++) {
                MMA16816(acc[mt][nt], ah[mt], bh[nt]);
                MMA16816(acc[mt][nt], ah[mt], bl[nt]);
                MMA16816(acc[mt][nt], al[mt], bh[nt]);
            }
        __syncthreads();
    }

    // epilogue: d0,d1 at (row fr, cols fc,fc+1); d2,d3 at row fr+8
    const int fr = lane >> 2;
    const int fc = (lane & 3) * 2;
#pragma unroll
    for (int mt = 0; mt < 4; mt++) {
#pragma unroll
        for (int nt = 0; nt < 4; nt++) {
            int r = wm * 64 + mt * 16 + fr;
            int c = wn * 32 + nt * 8 + fc;
            float d0 = acc[mt][nt][0], d1 = acc[mt][nt][1];
            float d2 = acc[mt][nt][2], d3 = acc[mt][nt][3];
            if (MODE == 0) {
                *(float2*)(g_z + (size_t)(t0 + r) * NC + o0 + c)     = make_float2(d0, d1);
                *(float2*)(g_z + (size_t)(t0 + r + 8) * NC + o0 + c) = make_float2(d2, d3);
            } else if (MODE == 1) {
                *(float2*)(g_v + (size_t)(t0 + r) * NC + o0 + c)     = make_float2(d0, d1);
                *(float2*)(g_v + (size_t)(t0 + r + 8) * NC + o0 + c) = make_float2(d2, d3);
            } else if (MODE == 2) {
#pragma unroll
                for (int h = 0; h < 2; h++) {
                    int rr = r + h * 8;
                    float e0 = (h ? d2 : d0), e1 = (h ? d3 : d1);
                    size_t base = (size_t)(t0 + rr) * NC + o0 + c;
                    float2 xv = *(const float2*)(g_xt + base);
                    float y0 = e0 + xv.x, y1 = e1 + xv.y;
                    __nv_bfloat16 h0 = __float2bfloat16(y0);
                    __nv_bfloat16 h1 = __float2bfloat16(y1);
                    __nv_bfloat162 hh; hh.x = h0; hh.y = h1;
                    *(__nv_bfloat162*)(g_yh + base) = hh;
                    __nv_bfloat162 ll;
                    ll.x = __float2bfloat16(y0 - __bfloat162float(h0));
                    ll.y = __float2bfloat16(y1 - __bfloat162float(h1));
                    *(__nv_bfloat162*)(g_yl + base) = ll;
                }
            } else {
                const int b = t0 >> 12;
                int l = (t0 & 4095) + r;
                outf[((size_t)(b * NOUT + o0 + c))     * NL + l] = d0;
                outf[((size_t)(b * NOUT + o0 + c + 1)) * NL + l] = d1;
                outf[((size_t)(b * NOUT + o0 + c))     * NL + l + 8] = d2;
                outf[((size_t)(b * NOUT + o0 + c + 1)) * NL + l + 8] = d3;
            }
        }
    }
}

// ================= K: per-l batch attention (x_t, z, v) + GN partials =================
#define QS_STR 260
#define KT_STR 65
#define AT_STR 66
#define SM_ATTN_FLOATS (64 * QS_STR + 256 * KT_STR + 64 * 256 + 64 * AT_STR)
#define SM_ATTN_BYTES  (SM_ATTN_FLOATS * 4)

__global__ __launch_bounds__(256) void k_attn()
{
    extern __shared__ float sm[];
    float* Qs  = sm;                       // [b][c] stride 260 (x)
    float* KsT = Qs + 64 * QS_STR;         // [c][d] stride 65 (z)
    float* Vs  = KsT + 256 * KT_STR;       // [d][c] stride 256 (v)
    float* att = Vs + 64 * 256;            // [b][d] stride 66

    const int l = blockIdx.x;
    const int tid = threadIdx.x;

    for (int idx = tid; idx < 64 * 64; idx += 256) {
        int row = idx >> 6;
        int c4  = (idx & 63) << 2;
        size_t g = ((size_t)row * NL + l) * NC + c4;
        float4 q = *(const float4*)(g_xt + g);
        *(float4*)&Qs[row * QS_STR + c4] = q;
        float4 k = *(const float4*)(g_z + g);
        KsT[(c4 + 0) * KT_STR + row] = k.x;
        KsT[(c4 + 1) * KT_STR + row] = k.y;
        KsT[(c4 + 2) * KT_STR + row] = k.z;
        KsT[(c4 + 3) * KT_STR + row] = k.w;
        float4 v = *(const float4*)(g_v + g);
        *(float4*)&Vs[row * 256 + c4] = v;
    }
    __syncthreads();

    const int tx = tid & 15, ty = tid >> 4;
    float acc[4][4];
#pragma unroll
    for (int i = 0; i < 4; i++)
#pragma unroll
        for (int j = 0; j < 4; j++) acc[i][j] = 0.f;

#pragma unroll 4
    for (int c = 0; c < NC; c++) {
        float a0 = Qs[(ty     ) * QS_STR + c];
        float a1 = Qs[(ty + 16) * QS_STR + c];
        float a2 = Qs[(ty + 32) * QS_STR + c];
        float a3 = Qs[(ty + 48) * QS_STR + c];
        const float* kc = KsT + c * KT_STR + tx;
        float b0 = kc[0], b1 = kc[16], b2 = kc[32], b3 = kc[48];
        acc[0][0] = fmaf(a0, b0, acc[0][0]); acc[0][1] = fmaf(a0, b1, acc[0][1]);
        acc[0][2] = fmaf(a0, b2, acc[0][2]); acc[0][3] = fmaf(a0, b3, acc[0][3]);
        acc[1][0] = fmaf(a1, b0, acc[1][0]); acc[1][1] = fmaf(a1, b1, acc[1][1]);
        acc[1][2] = fmaf(a1, b2, acc[1][2]); acc[1][3] = fmaf(a1, b3, acc[1][3]);
        acc[2][0] = fmaf(a2, b0, acc[2][0]); acc[2][1] = fmaf(a2, b1, acc[2][1]);
        acc[2][2] = fmaf(a2, b2, acc[2][2]); acc[2][3] = fmaf(a2, b3, acc[2][3]);
        acc[3][0] = fmaf(a3, b0, acc[3][0]); acc[3][1] = fmaf(a3, b1, acc[3][1]);
        acc[3][2] = fmaf(a3, b2, acc[3][2]); acc[3][3] = fmaf(a3, b3, acc[3][3]);
    }
#pragma unroll
    for (int i = 0; i < 4; i++)
#pragma unroll
        for (int j = 0; j < 4; j++)
            att[(ty + i * 16) * AT_STR + tx + j * 16] = acc[i][j] * 0.0625f;
    __syncthreads();

    if (tid < 64) {
        float* row = att + tid * AT_STR;
        float m = row[0];
        for (int d = 1; d < 64; d++) m = fmaxf(m, row[d]);
        float s = 0.f;
        for (int d = 0; d < 64; d++) { float e = __expf(row[d] - m); row[d] = e; s += e; }
        float inv = 1.f / s;
        for (int d = 0; d < 64; d++) row[d] *= inv;
    }
    __syncthreads();

    const int bb = tid >> 2;
    const int q4 = (tid & 3) << 2;
    float4 a4[16];
#pragma unroll
    for (int i = 0; i < 16; i++) a4[i] = make_float4(0.f, 0.f, 0.f, 0.f);

    for (int d = 0; d < 64; d++) {
        float w = att[bb * AT_STR + d];
        const float* vr = Vs + d * 256 + q4;
#pragma unroll
        for (int i = 0; i < 16; i++) {
            float4 v = *(const float4*)(vr + i * 16);
            a4[i].x = fmaf(w, v.x, a4[i].x);
            a4[i].y = fmaf(w, v.y, a4[i].y);
            a4[i].z = fmaf(w, v.z, a4[i].z);
            a4[i].w = fmaf(w, v.w, a4[i].w);
        }
    }

    float s = 0.f, ss = 0.f;
    float* vp = g_virt + ((size_t)bb * NL + l) * NC + q4;
#pragma unroll
    for (int i = 0; i < 16; i++) {
        *(float4*)(vp + i * 16) = a4[i];
        s  += a4[i].x + a4[i].y + a4[i].z + a4[i].w;
        ss += a4[i].x * a4[i].x + a4[i].y * a4[i].y + a4[i].z * a4[i].z + a4[i].w * a4[i].w;
    }
    s  += __shfl_xor_sync(0xffffffffu, s, 1);
    s  += __shfl_xor_sync(0xffffffffu, s, 2);
    ss += __shfl_xor_sync(0xffffffffu, ss, 1);
    ss += __shfl_xor_sync(0xffffffffu, ss, 2);
    if ((tid & 3) == 0) {
        atomicAdd(&g_psum[bb], s);
        atomicAdd(&g_psumsq[bb], ss);
    }
}

// ================= K: stats =================
__global__ void k_stats()
{
    int b = threadIdx.x;
    if (b < NB) {
        const float n = (float)NC * (float)NL;
        float mean = g_psum[b] / n;
        float var  = g_psumsq[b] / n - mean * mean;
        if (var < 0.f) var = 0.f;
        g_mean[b] = mean;
        g_rstd[b] = rsqrtf(var + 1e-5f);
    }
}

// ================= K: GN+ReLU on virt -> bf16 hi/lo =================
__global__ __launch_bounds__(256) void k_prep2(const float* __restrict__ gamma, const float* __restrict__ beta)
{
    size_t i4 = ((size_t)blockIdx.x * 256 + threadIdx.x) * 4;
    int c = (int)(i4 & 255);
    int b = (int)(i4 >> 20);
    float mean = g_mean[b], rstd = g_rstd[b];
    float4 v = *(const float4*)(g_virt + i4);
    float vv[4] = { v.x, v.y, v.z, v.w };
#pragma unroll
    for (int i = 0; i < 4; i++) {
        float y = fmaxf(fmaf((vv[i] - mean) * rstd, gamma[c + i], beta[c + i]), 0.f);
        __nv_bfloat16 h = __float2bfloat16(y);
        g_nh[i4 + i] = h;
        g_nl[i4 + i] = __float2bfloat16(y - __bfloat162float(h));
    }
}

// ================= launch =================
extern "C" void kernel_launch(void* const* d_in, const int* in_sizes, int n_in,
                              void* d_out, int out_size)
{
    const float* x     = (const float*)d_in[0];
    const float* Wq    = (const float*)d_in[1];
    const float* Wk    = (const float*)d_in[2];
    const float* Wv    = (const float*)d_in[3];
    const float* Wc    = (const float*)d_in[4];
    const float* Wout  = (const float*)d_in[5];
    const float* gamma = (const float*)d_in[6];
    const float* beta  = (const float*)d_in[7];
    float* out = (float*)d_out;

    cudaFuncSetAttribute(k_attn, cudaFuncAttributeMaxDynamicSharedMemorySize, SM_ATTN_BYTES);

    k_zero<<<1, 128>>>();
    k_prep0<<<dim3(64, 4, 64), 256>>>(x);
    k_gmat<<<16, 256>>>(Wq, Wk);
    k_prepw<<<192, 256>>>(Wv, Wc, Wout);
    k_gemm<0><<<dim3(2048, 2), 256>>>(nullptr);   // z = G x
    k_gemm<1><<<dim3(2048, 2), 256>>>(nullptr);   // v = Wv x
    k_attn<<<NL, 256, SM_ATTN_BYTES>>>();
    k_stats<<<1, 64>>>();
    k_prep2<<<65536, 256>>>(gamma, beta);
    k_gemm<2><<<dim3(2048, 2), 256>>>(nullptr);   // y = x + Wc(gn)
    k_gemm<3><<<dim3(2048, 2), 256>>>(out);       // out = Wout y
}

// round 8
// speedup vs baseline: 1.8386x; 1.5692x over previous
#include <cuda_runtime.h>
#include <cuda_bf16.h>
#include <cstdint>

#define NB   64
#define NC   256
#define NL   4096
#define NOUT 256
#define NTOK (NB * NL)   // 262144 tokens

// ================= helpers =================
__device__ __forceinline__ uint32_t smem_to_u32(const void* p) {
    uint32_t a;
    asm("{ .reg .u64 t; cvta.to.shared.u64 t, %1; cvt.u32.u64 %0, t; }" : "=r"(a) : "l"(p));
    return a;
}
__device__ __forceinline__ void cpa16(uint32_t s, const void* g) {
    asm volatile("cp.async.cg.shared.global [%0], [%1], 16;" :: "r"(s), "l"(g) : "memory");
}
__device__ __forceinline__ uint32_t lds32v(uint32_t a) {
    uint32_t v;
    asm volatile("ld.shared.b32 %0, [%1];" : "=r"(v) : "r"(a) : "memory");
    return v;
}
#define MMA16816(d, a, b) \
    asm volatile("mma.sync.aligned.m16n8k16.row.col.f32.bf16.bf16.f32 " \
        "{%0,%1,%2,%3},{%4,%5,%6,%7},{%8,%9},{%0,%1,%2,%3};" \
        : "+f"((d)[0]), "+f"((d)[1]), "+f"((d)[2]), "+f"((d)[3]) \
        : "r"((a)[0]), "r"((a)[1]), "r"((a)[2]), "r"((a)[3]), "r"((b)[0]), "r"((b)[1]))

// ================= scratch (device globals; referenced ONLY in device code) =================
__device__ __align__(256) float         g_xt  [(long long)NTOK * NC];
__device__ __align__(256) __nv_bfloat16 g_xh  [(long long)NTOK * NC];
__device__ __align__(256) __nv_bfloat16 g_xl  [(long long)NTOK * NC];
__device__ __align__(256) float         g_z   [(long long)NTOK * NC];
__device__ __align__(256) float         g_v   [(long long)NTOK * NC];
__device__ __align__(256) float         g_virt[(long long)NTOK * NC];
__device__ __align__(256) __nv_bfloat16 g_nh  [(long long)NTOK * NC];
__device__ __align__(256) __nv_bfloat16 g_nl  [(long long)NTOK * NC];
__device__ __align__(256) __nv_bfloat16 g_Gh[NC * NC],  g_Gl[NC * NC];
__device__ __align__(256) __nv_bfloat16 g_wvh[NC * NC], g_wvl[NC * NC];
__device__ __align__(256) __nv_bfloat16 g_woh[NC * NC], g_wol[NC * NC];
__device__ __align__(256) __nv_bfloat16 g_wzh[NC * NC], g_wzl[NC * NC];
__device__ float g_psum[NB], g_psumsq[NB], g_mean[NB], g_rstd[NB];

// ================= K: zero GN accumulators =================
__global__ void k_zero()
{
    int t = threadIdx.x;
    if (t < NB) { g_psum[t] = 0.f; g_psumsq[t] = 0.f; }
}

// ================= K: transpose x -> x_t (fp32) + bf16 hi/lo split =================
__global__ __launch_bounds__(256) void k_prep0(const float* __restrict__ x)
{
    __shared__ float tile[64][65];
    const int b  = blockIdx.z;
    const int l0 = blockIdx.x << 6;
    const int c0 = blockIdx.y << 6;
    const int tid = threadIdx.x;
    const int tx = tid & 63, ty = tid >> 6;

    const float* xp = x + (size_t)b * NC * NL + (size_t)c0 * NL + l0;
#pragma unroll
    for (int i = 0; i < 16; i++) {
        int r = i * 4 + ty;
        tile[r][tx] = xp[(size_t)r * NL + tx];
    }
    __syncthreads();
#pragma unroll
    for (int i = 0; i < 16; i++) {
        int lr = i * 4 + ty;
        float v = tile[tx][lr];
        size_t idx = ((size_t)(b * NL + l0 + lr)) * NC + c0 + tx;
        g_xt[idx] = v;
        __nv_bfloat16 h = __float2bfloat16(v);
        g_xh[idx] = h;
        g_xl[idx] = __float2bfloat16(v - __bfloat162float(h));
    }
}

// ================= K: G[e][f] = sum_o Wq[o][e] Wk[o][f], split bf16 hi/lo =================
__global__ __launch_bounds__(256) void k_gmatA(const float* __restrict__ Wq, const float* __restrict__ Wk)
{
    __shared__ float sA[16][68], sB[16][68];
    const int e0 = (blockIdx.x & 3) << 6;
    const int f0 = (blockIdx.x >> 2) << 6;
    const int tid = threadIdx.x;
    const int tx = tid & 15, ty = tid >> 4;

    float acc[4][4];
#pragma unroll
    for (int i = 0; i < 4; i++)
#pragma unroll
        for (int j = 0; j < 4; j++) acc[i][j] = 0.f;

    for (int k0 = 0; k0 < NC; k0 += 16) {
#pragma unroll
        for (int i = 0; i < 4; i++) {
            int r = (tid >> 6) + i * 4, col = tid & 63;
            sA[r][col] = Wq[(size_t)(k0 + r) * NC + e0 + col];
            sB[r][col] = Wk[(size_t)(k0 + r) * NC + f0 + col];
        }
        __syncthreads();
#pragma unroll
        for (int kk = 0; kk < 16; kk++) {
            float a[4], bb[4];
#pragma unroll
            for (int i = 0; i < 4; i++) { a[i] = sA[kk][ty * 4 + i]; bb[i] = sB[kk][tx * 4 + i]; }
#pragma unroll
            for (int i = 0; i < 4; i++)
#pragma unroll
                for (int j = 0; j < 4; j++) acc[i][j] = fmaf(a[i], bb[j], acc[i][j]);
        }
        __syncthreads();
    }
#pragma unroll
    for (int i = 0; i < 4; i++)
#pragma unroll
        for (int j = 0; j < 4; j++) {
            int e = e0 + ty * 4 + i, f = f0 + tx * 4 + j;
            float g = acc[i][j];
            __nv_bfloat16 h = __float2bfloat16(g);
            g_Gh[e * NC + f] = h;
            g_Gl[e * NC + f] = __float2bfloat16(g - __bfloat162float(h));
        }
}

// ================= K: Wz[o][c] = sum_m Wout[o][m] Wc[m][c], split bf16 hi/lo =================
__global__ __launch_bounds__(256) void k_gmatB(const float* __restrict__ Wo, const float* __restrict__ Wc)
{
    __shared__ float sA[16][68], sB[16][68];   // sA[m][o], sB[m][c]
    const int e0 = (blockIdx.x & 3) << 6;      // o tile
    const int f0 = (blockIdx.x >> 2) << 6;     // c tile
    const int tid = threadIdx.x;
    const int tx = tid & 15, ty = tid >> 4;

    float acc[4][4];
#pragma unroll
    for (int i = 0; i < 4; i++)
#pragma unroll
        for (int j = 0; j < 4; j++) acc[i][j] = 0.f;

    for (int k0 = 0; k0 < NC; k0 += 16) {
#pragma unroll
        for (int i = 0; i < 4; i++) {
            int r = (tid >> 6) + i * 4, col = tid & 63;
            sA[r][col] = Wo[(size_t)(e0 + col) * NC + k0 + r];   // transposed gather
            sB[r][col] = Wc[(size_t)(k0 + r) * NC + f0 + col];
        }
        __syncthreads();
#pragma unroll
        for (int kk = 0; kk < 16; kk++) {
            float a[4], bb[4];
#pragma unroll
            for (int i = 0; i < 4; i++) { a[i] = sA[kk][ty * 4 + i]; bb[i] = sB[kk][tx * 4 + i]; }
#pragma unroll
            for (int i = 0; i < 4; i++)
#pragma unroll
                for (int j = 0; j < 4; j++) acc[i][j] = fmaf(a[i], bb[j], acc[i][j]);
        }
        __syncthreads();
    }
#pragma unroll
    for (int i = 0; i < 4; i++)
#pragma unroll
        for (int j = 0; j < 4; j++) {
            int e = e0 + ty * 4 + i, f = f0 + tx * 4 + j;
            float g = acc[i][j];
            __nv_bfloat16 h = __float2bfloat16(g);
            g_wzh[e * NC + f] = h;
            g_wzl[e * NC + f] = __float2bfloat16(g - __bfloat162float(h));
        }
}

// ================= K: split Wv, Wout to bf16 hi/lo =================
__global__ __launch_bounds__(256) void k_prepw(
    const float* __restrict__ Wv, const float* __restrict__ Wo)
{
    int gid = blockIdx.x * 256 + threadIdx.x;      // 32768 threads, 4 floats each
    int arr = gid >> 14;
    int off = (gid & 16383) * 4;
    const float* src = (arr == 0) ? Wv : Wo;
    __nv_bfloat16* dh = (arr == 0) ? g_wvh : g_woh;
    __nv_bfloat16* dl = (arr == 0) ? g_wvl : g_wol;
    float4 v = *(const float4*)(src + off);
    float vv[4] = { v.x, v.y, v.z, v.w };
#pragma unroll
    for (int i = 0; i < 4; i++) {
        __nv_bfloat16 h = __float2bfloat16(vv[i]);
        dh[off + i] = h;
        dl[off + i] = __float2bfloat16(vv[i] - __bfloat162float(h));
    }
}

// ================= K: mma.sync bf16-split GEMM, 4-stage pipeline =================
// KIND 0: grid (2048, 4): y<2 -> z = G x ; y>=2 -> v = Wv x   (16 k-stages)
// KIND 1: grid (2048, 2): out = Wout x + Wz gn (K=512, 32 k-stages, transposed store)
#define ROWB    80
#define HALF_B  (128 * ROWB)     // 10240 per operand
#define STAGE_B (2 * HALF_B)     // 20480 per stage
#define NPIPE   4
#define SMEM_GEMM (NPIPE * STAGE_B)   // 81920

template<int KIND>
__global__ __launch_bounds__(256) void k_gemm(float* __restrict__ outf)
{
    extern __shared__ __align__(128) char smem[];
    const uint32_t sbase = smem_to_u32(smem);
    const int tid  = threadIdx.x;
    const int wid  = tid >> 5;
    const int lane = tid & 31;
    const int t0   = blockIdx.x << 7;
    const int NS   = (KIND == 0) ? 16 : 32;

    int o0, wsel = 0;
    if (KIND == 0) { wsel = blockIdx.y >> 1; o0 = (blockIdx.y & 1) << 7; }
    else           { o0 = blockIdx.y << 7; }

    const int wm = wid & 1;     // 2 warps over M (64 rows each)
    const int wn = wid >> 1;    // 4 warps over N (32 cols each)

    auto load_stage = [&](int s) {
        const __nv_bfloat16 *Ah, *Al, *Wh, *Wl;
        int k0;
        if (KIND == 0) {
            Ah = g_xh; Al = g_xl;
            Wh = wsel ? g_wvh : g_Gh;
            Wl = wsel ? g_wvl : g_Gl;
            k0 = s << 4;
        } else {
            if (s < 16) { Ah = g_xh; Al = g_xl; Wh = g_woh; Wl = g_wol; k0 = s << 4; }
            else        { Ah = g_nh; Al = g_nl; Wh = g_wzh; Wl = g_wzl; k0 = (s - 16) << 4; }
        }
        const uint32_t buf = sbase + (uint32_t)(s & (NPIPE - 1)) * STAGE_B;
#pragma unroll
        for (int i = 0; i < 2; i++) {
            int idx = tid + (i << 8);          // [0,512)
            int r = idx >> 2, ch = idx & 3;
            const __nv_bfloat16* srcA = ((ch < 2) ? Ah : Al) + (size_t)(t0 + r) * NC + k0 + ((ch & 1) << 3);
            cpa16(buf + (uint32_t)(r * ROWB + (ch << 4)), srcA);
            const __nv_bfloat16* srcW = ((ch < 2) ? Wh : Wl) + (size_t)(o0 + r) * NC + k0 + ((ch & 1) << 3);
            cpa16(buf + (uint32_t)HALF_B + (uint32_t)(r * ROWB + (ch << 4)), srcW);
        }
        asm volatile("cp.async.commit_group;" ::: "memory");
    };

    float acc[4][4][4];
#pragma unroll
    for (int a = 0; a < 4; a++)
#pragma unroll
        for (int b = 0; b < 4; b++)
#pragma unroll
            for (int c = 0; c < 4; c++) acc[a][b][c] = 0.f;

    const int rq = lane >> 2;          // 0..7
    const int p4 = (lane & 3) << 2;    // 0,4,8,12 bytes

    load_stage(0);
    load_stage(1);
    load_stage(2);

    for (int s = 0; s < NS; s++) {
        int rem = NS - 1 - s;
        if (rem >= 2)      asm volatile("cp.async.wait_group 2;" ::: "memory");
        else if (rem == 1) asm volatile("cp.async.wait_group 1;" ::: "memory");
        else               asm volatile("cp.async.wait_group 0;" ::: "memory");
        __syncthreads();
        if (s + 3 < NS) load_stage(s + 3);

        const uint32_t bufA = sbase + (uint32_t)(s & (NPIPE - 1)) * STAGE_B;
        const uint32_t bufW = bufA + (uint32_t)HALF_B;

        uint32_t ah[4][4], al[4][4], bh[4][2], bl[4][2];
#pragma unroll
        for (int mt = 0; mt < 4; mt++) {
            uint32_t base = bufA + (uint32_t)((wm * 64 + mt * 16 + rq) * ROWB + p4);
            ah[mt][0] = lds32v(base);
            ah[mt][1] = lds32v(base + 8 * ROWB);
            ah[mt][2] = lds32v(base + 16);
            ah[mt][3] = lds32v(base + 8 * ROWB + 16);
            al[mt][0] = lds32v(base + 32);
            al[mt][1] = lds32v(base + 8 * ROWB + 32);
            al[mt][2] = lds32v(base + 48);
            al[mt][3] = lds32v(base + 8 * ROWB + 48);
        }
#pragma unroll
        for (int nt = 0; nt < 4; nt++) {
            uint32_t base = bufW + (uint32_t)((wn * 32 + nt * 8 + rq) * ROWB + p4);
            bh[nt][0] = lds32v(base);
            bh[nt][1] = lds32v(base + 16);
            bl[nt][0] = lds32v(base + 32);
            bl[nt][1] = lds32v(base + 48);
        }
#pragma unroll
        for (int mt = 0; mt < 4; mt++)
#pragma unroll
            for (int nt = 0; nt < 4; nt++) {
                MMA16816(acc[mt][nt], ah[mt], bh[nt]);
                MMA16816(acc[mt][nt], ah[mt], bl[nt]);
                MMA16816(acc[mt][nt], al[mt], bh[nt]);
            }
    }

    // epilogue
    const int fr = lane >> 2;
    const int fc = (lane & 3) * 2;
#pragma unroll
    for (int mt = 0; mt < 4; mt++) {
#pragma unroll
        for (int nt = 0; nt < 4; nt++) {
            int r = wm * 64 + mt * 16 + fr;
            int c = wn * 32 + nt * 8 + fc;
            float d0 = acc[mt][nt][0], d1 = acc[mt][nt][1];
            float d2 = acc[mt][nt][2], d3 = acc[mt][nt][3];
            if (KIND == 0) {
                float* dst = wsel ? g_v : g_z;
                *(float2*)(dst + (size_t)(t0 + r) * NC + o0 + c)     = make_float2(d0, d1);
                *(float2*)(dst + (size_t)(t0 + r + 8) * NC + o0 + c) = make_float2(d2, d3);
            } else {
                const int b = t0 >> 12;
                int l = (t0 & 4095) + r;
                outf[((size_t)(b * NOUT + o0 + c))     * NL + l] = d0;
                outf[((size_t)(b * NOUT + o0 + c + 1)) * NL + l] = d1;
                outf[((size_t)(b * NOUT + o0 + c))     * NL + l + 8] = d2;
                outf[((size_t)(b * NOUT + o0 + c + 1)) * NL + l + 8] = d3;
            }
        }
    }
}

// ================= K: per-l batch attention (x_t, z, v) + GN partials =================
#define QS_STR 260
#define KT_STR 65
#define AT_STR 66
#define SM_ATTN_FLOATS (64 * QS_STR + 256 * KT_STR + 64 * 256 + 64 * AT_STR)
#define SM_ATTN_BYTES  (SM_ATTN_FLOATS * 4)

__global__ __launch_bounds__(256) void k_attn()
{
    extern __shared__ float sm[];
    float* Qs  = sm;                       // [b][c] stride 260 (x)
    float* KsT = Qs + 64 * QS_STR;         // [c][d] stride 65 (z)
    float* Vs  = KsT + 256 * KT_STR;       // [d][c] stride 256 (v)
    float* att = Vs + 64 * 256;            // [b][d] stride 66

    const int l = blockIdx.x;
    const int tid = threadIdx.x;

    for (int idx = tid; idx < 64 * 64; idx += 256) {
        int row = idx >> 6;
        int c4  = (idx & 63) << 2;
        size_t g = ((size_t)row * NL + l) * NC + c4;
        float4 q = *(const float4*)(g_xt + g);
        *(float4*)&Qs[row * QS_STR + c4] = q;
        float4 k = *(const float4*)(g_z + g);
        KsT[(c4 + 0) * KT_STR + row] = k.x;
        KsT[(c4 + 1) * KT_STR + row] = k.y;
        KsT[(c4 + 2) * KT_STR + row] = k.z;
        KsT[(c4 + 3) * KT_STR + row] = k.w;
        float4 v = *(const float4*)(g_v + g);
        *(float4*)&Vs[row * 256 + c4] = v;
    }
    __syncthreads();

    const int tx = tid & 15, ty = tid >> 4;
    float acc[4][4];
#pragma unroll
    for (int i = 0; i < 4; i++)
#pragma unroll
        for (int j = 0; j < 4; j++) acc[i][j] = 0.f;

#pragma unroll 4
    for (int c = 0; c < NC; c++) {
        float a0 = Qs[(ty     ) * QS_STR + c];
        float a1 = Qs[(ty + 16) * QS_STR + c];
        float a2 = Qs[(ty + 32) * QS_STR + c];
        float a3 = Qs[(ty + 48) * QS_STR + c];
        const float* kc = KsT + c * KT_STR + tx;
        float b0 = kc[0], b1 = kc[16], b2 = kc[32], b3 = kc[48];
        acc[0][0] = fmaf(a0, b0, acc[0][0]); acc[0][1] = fmaf(a0, b1, acc[0][1]);
        acc[0][2] = fmaf(a0, b2, acc[0][2]); acc[0][3] = fmaf(a0, b3, acc[0][3]);
        acc[1][0] = fmaf(a1, b0, acc[1][0]); acc[1][1] = fmaf(a1, b1, acc[1][1]);
        acc[1][2] = fmaf(a1, b2, acc[1][2]); acc[1][3] = fmaf(a1, b3, acc[1][3]);
        acc[2][0] = fmaf(a2, b0, acc[2][0]); acc[2][1] = fmaf(a2, b1, acc[2][1]);
        acc[2][2] = fmaf(a2, b2, acc[2][2]); acc[2][3] = fmaf(a2, b3, acc[2][3]);
        acc[3][0] = fmaf(a3, b0, acc[3][0]); acc[3][1] = fmaf(a3, b1, acc[3][1]);
        acc[3][2] = fmaf(a3, b2, acc[3][2]); acc[3][3] = fmaf(a3, b3, acc[3][3]);
    }
#pragma unroll
    for (int i = 0; i < 4; i++)
#pragma unroll
        for (int j = 0; j < 4; j++)
            att[(ty + i * 16) * AT_STR + tx + j * 16] = acc[i][j] * 0.0625f;
    __syncthreads();

    if (tid < 64) {
        float* row = att + tid * AT_STR;
        float m = row[0];
        for (int d = 1; d < 64; d++) m = fmaxf(m, row[d]);
        float s = 0.f;
        for (int d = 0; d < 64; d++) { float e = __expf(row[d] - m); row[d] = e; s += e; }
        float inv = 1.f / s;
        for (int d = 0; d < 64; d++) row[d] *= inv;
    }
    __syncthreads();

    const int bb = tid >> 2;
    const int q4 = (tid & 3) << 2;
    float4 a4[16];
#pragma unroll
    for (int i = 0; i < 16; i++) a4[i] = make_float4(0.f, 0.f, 0.f, 0.f);

    for (int d = 0; d < 64; d++) {
        float w = att[bb * AT_STR + d];
        const float* vr = Vs + d * 256 + q4;
#pragma unroll
        for (int i = 0; i < 16; i++) {
            float4 v = *(const float4*)(vr + i * 16);
            a4[i].x = fmaf(w, v.x, a4[i].x);
            a4[i].y = fmaf(w, v.y, a4[i].y);
            a4[i].z = fmaf(w, v.z, a4[i].z);
            a4[i].w = fmaf(w, v.w, a4[i].w);
        }
    }

    float s = 0.f, ss = 0.f;
    float* vp = g_virt + ((size_t)bb * NL + l) * NC + q4;
#pragma unroll
    for (int i = 0; i < 16; i++) {
        *(float4*)(vp + i * 16) = a4[i];
        s  += a4[i].x + a4[i].y + a4[i].z + a4[i].w;
        ss += a4[i].x * a4[i].x + a4[i].y * a4[i].y + a4[i].z * a4[i].z + a4[i].w * a4[i].w;
    }
    s  += __shfl_xor_sync(0xffffffffu, s, 1);
    s  += __shfl_xor_sync(0xffffffffu, s, 2);
    ss += __shfl_xor_sync(0xffffffffu, ss, 1);
    ss += __shfl_xor_sync(0xffffffffu, ss, 2);
    if ((tid & 3) == 0) {
        atomicAdd(&g_psum[bb], s);
        atomicAdd(&g_psumsq[bb], ss);
    }
}

// ================= K: stats =================
__global__ void k_stats()
{
    int b = threadIdx.x;
    if (b < NB) {
        const float n = (float)NC * (float)NL;
        float mean = g_psum[b] / n;
        float var  = g_psumsq[b] / n - mean * mean;
        if (var < 0.f) var = 0.f;
        g_mean[b] = mean;
        g_rstd[b] = rsqrtf(var + 1e-5f);
    }
}

// ================= K: GN+ReLU on virt -> bf16 hi/lo =================
__global__ __launch_bounds__(256) void k_prep2(const float* __restrict__ gamma, const float* __restrict__ beta)
{
    size_t i4 = ((size_t)blockIdx.x * 256 + threadIdx.x) * 4;
    int c = (int)(i4 & 255);
    int b = (int)(i4 >> 20);
    float mean = g_mean[b], rstd = g_rstd[b];
    float4 v = *(const float4*)(g_virt + i4);
    float vv[4] = { v.x, v.y, v.z, v.w };
#pragma unroll
    for (int i = 0; i < 4; i++) {
        float y = fmaxf(fmaf((vv[i] - mean) * rstd, gamma[c + i], beta[c + i]), 0.f);
        __nv_bfloat16 h = __float2bfloat16(y);
        g_nh[i4 + i] = h;
        g_nl[i4 + i] = __float2bfloat16(y - __bfloat162float(h));
    }
}

// ================= launch =================
extern "C" void kernel_launch(void* const* d_in, const int* in_sizes, int n_in,
                              void* d_out, int out_size)
{
    const float* x     = (const float*)d_in[0];
    const float* Wq    = (const float*)d_in[1];
    const float* Wk    = (const float*)d_in[2];
    const float* Wv    = (const float*)d_in[3];
    const float* Wc    = (const float*)d_in[4];
    const float* Wout  = (const float*)d_in[5];
    const float* gamma = (const float*)d_in[6];
    const float* beta  = (const float*)d_in[7];
    float* out = (float*)d_out;

    cudaFuncSetAttribute(k_attn,    cudaFuncAttributeMaxDynamicSharedMemorySize, SM_ATTN_BYTES);
    cudaFuncSetAttribute(k_gemm<0>, cudaFuncAttributeMaxDynamicSharedMemorySize, SMEM_GEMM);
    cudaFuncSetAttribute(k_gemm<1>, cudaFuncAttributeMaxDynamicSharedMemorySize, SMEM_GEMM);

    k_zero<<<1, 128>>>();
    k_prep0<<<dim3(64, 4, 64), 256>>>(x);
    k_gmatA<<<16, 256>>>(Wq, Wk);
    k_gmatB<<<16, 256>>>(Wout, Wc);
    k_prepw<<<128, 256>>>(Wv, Wout);
    k_gemm<0><<<dim3(2048, 4), 256, SMEM_GEMM>>>(nullptr);   // z = G x ; v = Wv x
    k_attn<<<NL, 256, SM_ATTN_BYTES>>>();
    k_stats<<<1, 64>>>();
    k_prep2<<<65536, 256>>>(gamma, beta);
    k_gemm<1><<<dim3(2048, 2), 256, SMEM_GEMM>>>(out);       // out = Wout x + Wz gn
}

// round 9
// speedup vs baseline: 2.4187x; 1.3155x over previous
#include <cuda_runtime.h>
#include <cuda_bf16.h>
#include <cstdint>

#define NB   64
#define NC   256
#define NL   4096
#define NOUT 256
#define NTOK (NB * NL)   // 262144 tokens

// ================= helpers =================
__device__ __forceinline__ uint32_t smem_to_u32(const void* p) {
    uint32_t a;
    asm("{ .reg .u64 t; cvta.to.shared.u64 t, %1; cvt.u32.u64 %0, t; }" : "=r"(a) : "l"(p));
    return a;
}
__device__ __forceinline__ void cpa16(uint32_t s, const void* g) {
    asm volatile("cp.async.cg.shared.global [%0], [%1], 16;" :: "r"(s), "l"(g) : "memory");
}
__device__ __forceinline__ uint32_t lds32v(uint32_t a) {
    uint32_t v;
    asm volatile("ld.shared.b32 %0, [%1];" : "=r"(v) : "r"(a) : "memory");
    return v;
}
__device__ __forceinline__ uint32_t lds_u16pair(uint32_t a0, uint32_t a1) {
    uint32_t lo, hi;
    asm volatile("ld.shared.u16 %0, [%1];" : "=r"(lo) : "r"(a0) : "memory");
    asm volatile("ld.shared.u16 %0, [%1];" : "=r"(hi) : "r"(a1) : "memory");
    return lo | (hi << 16);
}
#define MMA16816(d, a, b) \
    asm volatile("mma.sync.aligned.m16n8k16.row.col.f32.bf16.bf16.f32 " \
        "{%0,%1,%2,%3},{%4,%5,%6,%7},{%8,%9},{%0,%1,%2,%3};" \
        : "+f"((d)[0]), "+f"((d)[1]), "+f"((d)[2]), "+f"((d)[3]) \
        : "r"((a)[0]), "r"((a)[1]), "r"((a)[2]), "r"((a)[3]), "r"((b)[0]), "r"((b)[1]))

// ================= scratch (device globals; referenced ONLY in device code) =================
__device__ __align__(256) __nv_bfloat16 g_xh  [(long long)NTOK * NC];
__device__ __align__(256) __nv_bfloat16 g_xl  [(long long)NTOK * NC];
__device__ __align__(256) __nv_bfloat16 g_zh  [(long long)NTOK * NC];
__device__ __align__(256) __nv_bfloat16 g_zl  [(long long)NTOK * NC];
__device__ __align__(256) __nv_bfloat16 g_vh  [(long long)NTOK * NC];
__device__ __align__(256) __nv_bfloat16 g_vl  [(long long)NTOK * NC];
__device__ __align__(256) float         g_virt[(long long)NTOK * NC];
__device__ __align__(256) __nv_bfloat16 g_nh  [(long long)NTOK * NC];
__device__ __align__(256) __nv_bfloat16 g_nl  [(long long)NTOK * NC];
__device__ __align__(256) __nv_bfloat16 g_Gh[NC * NC],  g_Gl[NC * NC];
__device__ __align__(256) __nv_bfloat16 g_wvh[NC * NC], g_wvl[NC * NC];
__device__ __align__(256) __nv_bfloat16 g_woh[NC * NC], g_wol[NC * NC];
__device__ __align__(256) __nv_bfloat16 g_wzh[NC * NC], g_wzl[NC * NC];
__device__ float g_psum[NB], g_psumsq[NB], g_mean[NB], g_rstd[NB];

// ================= K: zero GN accumulators =================
__global__ void k_zero()
{
    int t = threadIdx.x;
    if (t < NB) { g_psum[t] = 0.f; g_psumsq[t] = 0.f; }
}

// ================= K: transpose x -> bf16 hi/lo split (token-major) =================
__global__ __launch_bounds__(256) void k_prep0(const float* __restrict__ x)
{
    __shared__ float tile[64][65];
    const int b  = blockIdx.z;
    const int l0 = blockIdx.x << 6;
    const int c0 = blockIdx.y << 6;
    const int tid = threadIdx.x;
    const int tx = tid & 63, ty = tid >> 6;

    const float* xp = x + (size_t)b * NC * NL + (size_t)c0 * NL + l0;
#pragma unroll
    for (int i = 0; i < 16; i++) {
        int r = i * 4 + ty;
        tile[r][tx] = xp[(size_t)r * NL + tx];
    }
    __syncthreads();
#pragma unroll
    for (int i = 0; i < 16; i++) {
        int lr = i * 4 + ty;
        float v = tile[tx][lr];
        size_t idx = ((size_t)(b * NL + l0 + lr)) * NC + c0 + tx;
        __nv_bfloat16 h = __float2bfloat16(v);
        g_xh[idx] = h;
        g_xl[idx] = __float2bfloat16(v - __bfloat162float(h));
    }
}

// ================= K: G[e][f] = sum_o Wq[o][e] Wk[o][f], split bf16 hi/lo =================
__global__ __launch_bounds__(256) void k_gmatA(const float* __restrict__ Wq, const float* __restrict__ Wk)
{
    __shared__ float sA[16][68], sB[16][68];
    const int e0 = (blockIdx.x & 3) << 6;
    const int f0 = (blockIdx.x >> 2) << 6;
    const int tid = threadIdx.x;
    const int tx = tid & 15, ty = tid >> 4;

    float acc[4][4];
#pragma unroll
    for (int i = 0; i < 4; i++)
#pragma unroll
        for (int j = 0; j < 4; j++) acc[i][j] = 0.f;

    for (int k0 = 0; k0 < NC; k0 += 16) {
#pragma unroll
        for (int i = 0; i < 4; i++) {
            int r = (tid >> 6) + i * 4, col = tid & 63;
            sA[r][col] = Wq[(size_t)(k0 + r) * NC + e0 + col];
            sB[r][col] = Wk[(size_t)(k0 + r) * NC + f0 + col];
        }
        __syncthreads();
#pragma unroll
        for (int kk = 0; kk < 16; kk++) {
            float a[4], bb[4];
#pragma unroll
            for (int i = 0; i < 4; i++) { a[i] = sA[kk][ty * 4 + i]; bb[i] = sB[kk][tx * 4 + i]; }
#pragma unroll
            for (int i = 0; i < 4; i++)
#pragma unroll
                for (int j = 0; j < 4; j++) acc[i][j] = fmaf(a[i], bb[j], acc[i][j]);
        }
        __syncthreads();
    }
#pragma unroll
    for (int i = 0; i < 4; i++)
#pragma unroll
        for (int j = 0; j < 4; j++) {
            int e = e0 + ty * 4 + i, f = f0 + tx * 4 + j;
            float g = acc[i][j];
            __nv_bfloat16 h = __float2bfloat16(g);
            g_Gh[e * NC + f] = h;
            g_Gl[e * NC + f] = __float2bfloat16(g - __bfloat162float(h));
        }
}

// ================= K: Wz[o][c] = sum_m Wout[o][m] Wc[m][c], split bf16 hi/lo =================
__global__ __launch_bounds__(256) void k_gmatB(const float* __restrict__ Wo, const float* __restrict__ Wc)
{
    __shared__ float sA[16][68], sB[16][68];
    const int e0 = (blockIdx.x & 3) << 6;      // o tile
    const int f0 = (blockIdx.x >> 2) << 6;     // c tile
    const int tid = threadIdx.x;
    const int tx = tid & 15, ty = tid >> 4;

    float acc[4][4];
#pragma unroll
    for (int i = 0; i < 4; i++)
#pragma unroll
        for (int j = 0; j < 4; j++) acc[i][j] = 0.f;

    for (int k0 = 0; k0 < NC; k0 += 16) {
#pragma unroll
        for (int i = 0; i < 4; i++) {
            int r = (tid >> 6) + i * 4, col = tid & 63;
            sA[r][col] = Wo[(size_t)(e0 + col) * NC + k0 + r];   // transposed gather
            sB[r][col] = Wc[(size_t)(k0 + r) * NC + f0 + col];
        }
        __syncthreads();
#pragma unroll
        for (int kk = 0; kk < 16; kk++) {
            float a[4], bb[4];
#pragma unroll
            for (int i = 0; i < 4; i++) { a[i] = sA[kk][ty * 4 + i]; bb[i] = sB[kk][tx * 4 + i]; }
#pragma unroll
            for (int i = 0; i < 4; i++)
#pragma unroll
                for (int j = 0; j < 4; j++) acc[i][j] = fmaf(a[i], bb[j], acc[i][j]);
        }
        __syncthreads();
    }
#pragma unroll
    for (int i = 0; i < 4; i++)
#pragma unroll
        for (int j = 0; j < 4; j++) {
            int e = e0 + ty * 4 + i, f = f0 + tx * 4 + j;
            float g = acc[i][j];
            __nv_bfloat16 h = __float2bfloat16(g);
            g_wzh[e * NC + f] = h;
            g_wzl[e * NC + f] = __float2bfloat16(g - __bfloat162float(h));
        }
}

// ================= K: split Wv, Wout to bf16 hi/lo =================
__global__ __launch_bounds__(256) void k_prepw(
    const float* __restrict__ Wv, const float* __restrict__ Wo)
{
    int gid = blockIdx.x * 256 + threadIdx.x;
    int arr = gid >> 14;
    int off = (gid & 16383) * 4;
    const float* src = (arr == 0) ? Wv : Wo;
    __nv_bfloat16* dh = (arr == 0) ? g_wvh : g_woh;
    __nv_bfloat16* dl = (arr == 0) ? g_wvl : g_wol;
    float4 v = *(const float4*)(src + off);
    float vv[4] = { v.x, v.y, v.z, v.w };
#pragma unroll
    for (int i = 0; i < 4; i++) {
        __nv_bfloat16 h = __float2bfloat16(vv[i]);
        dh[off + i] = h;
        dl[off + i] = __float2bfloat16(vv[i] - __bfloat162float(h));
    }
}

// ================= K: mma.sync bf16-split GEMM, 4-stage pipeline =================
// KIND 0: grid (2048, 4): y<2 -> z = G x (bf16-split out) ; y>=2 -> v = Wv x (bf16-split out)
// KIND 1: grid (2048, 2): out = Wout x + Wz gn (K=512, transposed store)
#define ROWB    80
#define HALF_B  (128 * ROWB)
#define STAGE_B (2 * HALF_B)
#define NPIPE   4
#define SMEM_GEMM (NPIPE * STAGE_B)   // 81920

template<int KIND>
__global__ __launch_bounds__(256) void k_gemm(float* __restrict__ outf)
{
    extern __shared__ __align__(128) char smem[];
    const uint32_t sbase = smem_to_u32(smem);
    const int tid  = threadIdx.x;
    const int wid  = tid >> 5;
    const int lane = tid & 31;
    const int t0   = blockIdx.x << 7;
    const int NS   = (KIND == 0) ? 16 : 32;

    int o0, wsel = 0;
    if (KIND == 0) { wsel = blockIdx.y >> 1; o0 = (blockIdx.y & 1) << 7; }
    else           { o0 = blockIdx.y << 7; }

    const int wm = wid & 1;
    const int wn = wid >> 1;

    auto load_stage = [&](int s) {
        const __nv_bfloat16 *Ah, *Al, *Wh, *Wl;
        int k0;
        if (KIND == 0) {
            Ah = g_xh; Al = g_xl;
            Wh = wsel ? g_wvh : g_Gh;
            Wl = wsel ? g_wvl : g_Gl;
            k0 = s << 4;
        } else {
            if (s < 16) { Ah = g_xh; Al = g_xl; Wh = g_woh; Wl = g_wol; k0 = s << 4; }
            else        { Ah = g_nh; Al = g_nl; Wh = g_wzh; Wl = g_wzl; k0 = (s - 16) << 4; }
        }
        const uint32_t buf = sbase + (uint32_t)(s & (NPIPE - 1)) * STAGE_B;
#pragma unroll
        for (int i = 0; i < 2; i++) {
            int idx = tid + (i << 8);
            int r = idx >> 2, ch = idx & 3;
            const __nv_bfloat16* srcA = ((ch < 2) ? Ah : Al) + (size_t)(t0 + r) * NC + k0 + ((ch & 1) << 3);
            cpa16(buf + (uint32_t)(r * ROWB + (ch << 4)), srcA);
            const __nv_bfloat16* srcW = ((ch < 2) ? Wh : Wl) + (size_t)(o0 + r) * NC + k0 + ((ch & 1) << 3);
            cpa16(buf + (uint32_t)HALF_B + (uint32_t)(r * ROWB + (ch << 4)), srcW);
        }
        asm volatile("cp.async.commit_group;" ::: "memory");
    };

    float acc[4][4][4];
#pragma unroll
    for (int a = 0; a < 4; a++)
#pragma unroll
        for (int b = 0; b < 4; b++)
#pragma unroll
            for (int c = 0; c < 4; c++) acc[a][b][c] = 0.f;

    const int rq = lane >> 2;
    const int p4 = (lane & 3) << 2;

    load_stage(0);
    load_stage(1);
    load_stage(2);

    for (int s = 0; s < NS; s++) {
        int rem = NS - 1 - s;
        if (rem >= 2)      asm volatile("cp.async.wait_group 2;" ::: "memory");
        else if (rem == 1) asm volatile("cp.async.wait_group 1;" ::: "memory");
        else               asm volatile("cp.async.wait_group 0;" ::: "memory");
        __syncthreads();
        if (s + 3 < NS) load_stage(s + 3);

        const uint32_t bufA = sbase + (uint32_t)(s & (NPIPE - 1)) * STAGE_B;
        const uint32_t bufW = bufA + (uint32_t)HALF_B;

        uint32_t ah[4][4], al[4][4], bh[4][2], bl[4][2];
#pragma unroll
        for (int mt = 0; mt < 4; mt++) {
            uint32_t base = bufA + (uint32_t)((wm * 64 + mt * 16 + rq) * ROWB + p4);
            ah[mt][0] = lds32v(base);
            ah[mt][1] = lds32v(base + 8 * ROWB);
            ah[mt][2] = lds32v(base + 16);
            ah[mt][3] = lds32v(base + 8 * ROWB + 16);
            al[mt][0] = lds32v(base + 32);
            al[mt][1] = lds32v(base + 8 * ROWB + 32);
            al[mt][2] = lds32v(base + 48);
            al[mt][3] = lds32v(base + 8 * ROWB + 48);
        }
#pragma unroll
        for (int nt = 0; nt < 4; nt++) {
            uint32_t base = bufW + (uint32_t)((wn * 32 + nt * 8 + rq) * ROWB + p4);
            bh[nt][0] = lds32v(base);
            bh[nt][1] = lds32v(base + 16);
            bl[nt][0] = lds32v(base + 32);
            bl[nt][1] = lds32v(base + 48);
        }
#pragma unroll
        for (int mt = 0; mt < 4; mt++)
#pragma unroll
            for (int nt = 0; nt < 4; nt++) {
                MMA16816(acc[mt][nt], ah[mt], bh[nt]);
                MMA16816(acc[mt][nt], ah[mt], bl[nt]);
                MMA16816(acc[mt][nt], al[mt], bh[nt]);
            }
    }

    // epilogue
    const int fr = lane >> 2;
    const int fc = (lane & 3) * 2;
#pragma unroll
    for (int mt = 0; mt < 4; mt++) {
#pragma unroll
        for (int nt = 0; nt < 4; nt++) {
            int r = wm * 64 + mt * 16 + fr;
            int c = wn * 32 + nt * 8 + fc;
            float d0 = acc[mt][nt][0], d1 = acc[mt][nt][1];
            float d2 = acc[mt][nt][2], d3 = acc[mt][nt][3];
            if (KIND == 0) {
                __nv_bfloat16* dh = wsel ? g_vh : g_zh;
                __nv_bfloat16* dl = wsel ? g_vl : g_zl;
#pragma unroll
                for (int h = 0; h < 2; h++) {
                    float e0 = h ? d2 : d0, e1 = h ? d3 : d1;
                    size_t base = (size_t)(t0 + r + h * 8) * NC + o0 + c;
                    __nv_bfloat16 h0 = __float2bfloat16(e0);
                    __nv_bfloat16 h1 = __float2bfloat16(e1);
                    __nv_bfloat162 hh; hh.x = h0; hh.y = h1;
                    *(__nv_bfloat162*)(dh + base) = hh;
                    __nv_bfloat162 ll;
                    ll.x = __float2bfloat16(e0 - __bfloat162float(h0));
                    ll.y = __float2bfloat16(e1 - __bfloat162float(h1));
                    *(__nv_bfloat162*)(dl + base) = ll;
                }
            } else {
                const int b = t0 >> 12;
                int l = (t0 & 4095) + r;
                outf[((size_t)(b * NOUT + o0 + c))     * NL + l] = d0;
                outf[((size_t)(b * NOUT + o0 + c + 1)) * NL + l] = d1;
                outf[((size_t)(b * NOUT + o0 + c))     * NL + l + 8] = d2;
                outf[((size_t)(b * NOUT + o0 + c + 1)) * NL + l + 8] = d3;
            }
        }
    }
}

// ================= K: tensorized per-l batch attention + GN partials =================
// smem layout (bytes from base):
//   Qh 0, Ql 33792, Kh 67584, Kl 101376      (64 rows x 528B; 256 bf16 + pad)
//   S  135168  (fp32 [64][68]) — reused as GN accum after softmax
//   AH 152576, AL 161792  (att bf16, 64 rows x 144B)
//   V  171008: VH0, VL0, VH1, VL1 (each 64 rows x 144B = 9216B)
#define OF_QH 0
#define OF_QL 33792
#define OF_KH 67584
#define OF_KL 101376
#define OF_S  135168
#define OF_AH 152576
#define OF_AL 161792
#define OF_V  171008
#define SM_ATTN_BYTES (OF_V + 4 * 9216)   // 207872

__global__ __launch_bounds__(256) void k_attn()
{
    extern __shared__ __align__(128) char smc[];
    const uint32_t S0 = smem_to_u32(smc);
    float* smf = (float*)smc;
    const int l = blockIdx.x;
    const int tid = threadIdx.x;
    const int wid = tid >> 5, lane = tid & 31;
    const int rq = lane >> 2, p4 = (lane & 3) << 2;
    const int m0 = (wid & 3) * 16;
    const int n0 = (wid >> 2) * 32;

    // ---- load Q(x) and K(z), hi/lo ----
    for (int idx = tid; idx < 2048; idx += 256) {
        int row = idx >> 5, ch = idx & 31;
        size_t g = ((size_t)row * NL + l) * NC + ch * 8;
        uint32_t so = (uint32_t)(row * 528 + ch * 16);
        cpa16(S0 + OF_QH + so, g_xh + g);
        cpa16(S0 + OF_QL + so, g_xl + g);
        cpa16(S0 + OF_KH + so, g_zh + g);
        cpa16(S0 + OF_KL + so, g_zl + g);
    }
    // V chunk 0 into buffer 0
    for (int idx = tid; idx < 512; idx += 256) {
        int d = idx >> 3, ch = idx & 7;
        size_t g = ((size_t)d * NL + l) * NC + ch * 8;
        uint32_t so = (uint32_t)(d * 144 + ch * 16);
        cpa16(S0 + OF_V + so, g_vh + g);
        cpa16(S0 + OF_V + 9216 + so, g_vl + g);
    }
    asm volatile("cp.async.commit_group;" ::: "memory");
    asm volatile("cp.async.wait_group 0;" ::: "memory");
    __syncthreads();

    // ---- scores S[b][d] = (x_b . z_d) / 16, 3-term bf16 split ----
    float acc[4][4];
#pragma unroll
    for (int i = 0; i < 4; i++)
#pragma unroll
        for (int j = 0; j < 4; j++) acc[i][j] = 0.f;

#pragma unroll
    for (int kk = 0; kk < 16; kk++) {
        uint32_t abase = S0 + (uint32_t)((m0 + rq) * 528 + kk * 32 + p4);
        uint32_t ah[4], al[4];
        ah[0] = lds32v(abase + OF_QH);
        ah[1] = lds32v(abase + OF_QH + 8 * 528);
        ah[2] = lds32v(abase + OF_QH + 16);
        ah[3] = lds32v(abase + OF_QH + 8 * 528 + 16);
        al[0] = lds32v(abase + OF_QL);
        al[1] = lds32v(abase + OF_QL + 8 * 528);
        al[2] = lds32v(abase + OF_QL + 16);
        al[3] = lds32v(abase + OF_QL + 8 * 528 + 16);
#pragma unroll
        for (int nt = 0; nt < 4; nt++) {
            uint32_t bbase = S0 + (uint32_t)((n0 + nt * 8 + rq) * 528 + kk * 32 + p4);
            uint32_t bh[2], bl[2];
            bh[0] = lds32v(bbase + OF_KH);
            bh[1] = lds32v(bbase + OF_KH + 16);
            bl[0] = lds32v(bbase + OF_KL);
            bl[1] = lds32v(bbase + OF_KL + 16);
            MMA16816(acc[nt], ah, bh);
            MMA16816(acc[nt], ah, bl);
            MMA16816(acc[nt], al, bh);
        }
    }
    // store S (scaled)
#pragma unroll
    for (int nt = 0; nt < 4; nt++) {
        int r = m0 + rq;
        int c = n0 + nt * 8 + (lane & 3) * 2;
        *(float2*)&smf[(OF_S >> 2) + r * 68 + c]       = make_float2(acc[nt][0] * 0.0625f, acc[nt][1] * 0.0625f);
        *(float2*)&smf[(OF_S >> 2) + (r + 8) * 68 + c] = make_float2(acc[nt][2] * 0.0625f, acc[nt][3] * 0.0625f);
    }
    __syncthreads();

    // ---- softmax over d, write att as bf16 hi/lo ----
    if (tid < 64) {
        float* row = &smf[(OF_S >> 2) + tid * 68];
        float m = row[0];
        for (int d = 1; d < 64; d++) m = fmaxf(m, row[d]);
        float s = 0.f;
        float e[64];
        for (int d = 0; d < 64; d++) { e[d] = __expf(row[d] - m); s += e[d]; }
        float inv = 1.f / s;
        uint32_t ab = S0 + (uint32_t)(tid * 144);
        for (int d = 0; d < 64; d += 2) {
            float w0 = e[d] * inv, w1 = e[d + 1] * inv;
            __nv_bfloat16 h0 = __float2bfloat16(w0);
            __nv_bfloat16 h1 = __float2bfloat16(w1);
            __nv_bfloat162 hh; hh.x = h0; hh.y = h1;
            *(__nv_bfloat162*)(smc + OF_AH + tid * 144 + d * 2) = hh;
            __nv_bfloat162 ll;
            ll.x = __float2bfloat16(w0 - __bfloat162float(h0));
            ll.y = __float2bfloat16(w1 - __bfloat162float(h1));
            *(__nv_bfloat162*)(smc + OF_AL + tid * 144 + d * 2) = ll;
        }
        // init GN accumulators (reuse S region)
        smf[(OF_S >> 2) + tid] = 0.f;        // sum
        smf[(OF_S >> 2) + 64 + tid] = 0.f;   // sumsq
    }

    // ---- AV: virt[b][c] = sum_d att[b][d] v[d][c], chunked over c ----
    float gs0 = 0.f, gss0 = 0.f, gs1 = 0.f, gss1 = 0.f;

    for (int cc = 0; cc < 4; cc++) {
        __syncthreads();
        if (cc < 3) {
            int nb = (cc + 1) & 1;
            for (int idx = tid; idx < 512; idx += 256) {
                int d = idx >> 3, ch = idx & 7;
                size_t g = ((size_t)d * NL + l) * NC + (cc + 1) * 64 + ch * 8;
                uint32_t so = (uint32_t)(nb * 18432 + d * 144 + ch * 16);
                cpa16(S0 + OF_V + so, g_vh + g);
                cpa16(S0 + OF_V + 9216 + so, g_vl + g);
            }
            asm volatile("cp.async.commit_group;" ::: "memory");
            asm volatile("cp.async.wait_group 1;" ::: "memory");
        } else {
            asm volatile("cp.async.wait_group 0;" ::: "memory");
        }
        __syncthreads();

        const uint32_t VHb = S0 + OF_V + (uint32_t)((cc & 1) * 18432);
        const uint32_t VLb = VHb + 9216;

        float av[4][4];
#pragma unroll
        for (int i = 0; i < 4; i++)
#pragma unroll
            for (int j = 0; j < 4; j++) av[i][j] = 0.f;

#pragma unroll
        for (int k = 0; k < 4; k++) {
            uint32_t abase = S0 + (uint32_t)((m0 + rq) * 144 + k * 32 + p4);
            uint32_t ah[4], al[4];
            ah[0] = lds32v(abase + OF_AH);
            ah[1] = lds32v(abase + OF_AH + 8 * 144);
            ah[2] = lds32v(abase + OF_AH + 16);
            ah[3] = lds32v(abase + OF_AH + 8 * 144 + 16);
            al[0] = lds32v(abase + OF_AL);
            al[1] = lds32v(abase + OF_AL + 8 * 144);
            al[2] = lds32v(abase + OF_AL + 16);
            al[3] = lds32v(abase + OF_AL + 8 * 144 + 16);
            int d0 = k * 16 + (lane & 3) * 2;
#pragma unroll
            for (int nt = 0; nt < 4; nt++) {
                int c = n0 + nt * 8 + rq;
                uint32_t a0 = VHb + (uint32_t)(d0 * 144 + c * 2);
                uint32_t bh[2], bl[2];
                bh[0] = lds_u16pair(a0, a0 + 144);
                bh[1] = lds_u16pair(a0 + 8 * 144, a0 + 9 * 144);
                uint32_t a1 = VLb + (uint32_t)(d0 * 144 + c * 2);
                bl[0] = lds_u16pair(a1, a1 + 144);
                bl[1] = lds_u16pair(a1 + 8 * 144, a1 + 9 * 144);
                MMA16816(av[nt], ah, bh);
                MMA16816(av[nt], ah, bl);
                MMA16816(av[nt], al, bh);
            }
        }
        // store virt chunk + GN partials
#pragma unroll
        for (int nt = 0; nt < 4; nt++) {
            int b0r = m0 + rq;
            int c = cc * 64 + n0 + nt * 8 + (lane & 3) * 2;
            float2 v01 = make_float2(av[nt][0], av[nt][1]);
            float2 v23 = make_float2(av[nt][2], av[nt][3]);
            *(float2*)(g_virt + ((size_t)b0r * NL + l) * NC + c)       = v01;
            *(float2*)(g_virt + ((size_t)(b0r + 8) * NL + l) * NC + c) = v23;
            gs0  += v01.x + v01.y;
            gss0 += v01.x * v01.x + v01.y * v01.y;
            gs1  += v23.x + v23.y;
            gss1 += v23.x * v23.x + v23.y * v23.y;
        }
    }

    // reduce GN partials over lane&3, accumulate into smem, then global atomics
    gs0  += __shfl_xor_sync(0xffffffffu, gs0, 1);  gs0  += __shfl_xor_sync(0xffffffffu, gs0, 2);
    gss0 += __shfl_xor_sync(0xffffffffu, gss0, 1); gss0 += __shfl_xor_sync(0xffffffffu, gss0, 2);
    gs1  += __shfl_xor_sync(0xffffffffu, gs1, 1);  gs1  += __shfl_xor_sync(0xffffffffu, gs1, 2);
    gss1 += __shfl_xor_sync(0xffffffffu, gss1, 1); gss1 += __shfl_xor_sync(0xffffffffu, gss1, 2);
    if ((lane & 3) == 0) {
        atomicAdd(&smf[(OF_S >> 2) + m0 + rq], gs0);
        atomicAdd(&smf[(OF_S >> 2) + 64 + m0 + rq], gss0);
        atomicAdd(&smf[(OF_S >> 2) + m0 + rq + 8], gs1);
        atomicAdd(&smf[(OF_S >> 2) + 64 + m0 + rq + 8], gss1);
    }
    __syncthreads();
    if (tid < 64) {
        atomicAdd(&g_psum[tid],   smf[(OF_S >> 2) + tid]);
        atomicAdd(&g_psumsq[tid], smf[(OF_S >> 2) + 64 + tid]);
    }
}

// ================= K: stats =================
__global__ void k_stats()
{
    int b = threadIdx.x;
    if (b < NB) {
        const float n = (float)NC * (float)NL;
        float mean = g_psum[b] / n;
        float var  = g_psumsq[b] / n - mean * mean;
        if (var < 0.f) var = 0.f;
        g_mean[b] = mean;
        g_rstd[b] = rsqrtf(var + 1e-5f);
    }
}

// ================= K: GN+ReLU on virt -> bf16 hi/lo =================
__global__ __launch_bounds__(256) void k_prep2(const float* __restrict__ gamma, const float* __restrict__ beta)
{
    size_t i4 = ((size_t)blockIdx.x * 256 + threadIdx.x) * 4;
    int c = (int)(i4 & 255);
    int b = (int)(i4 >> 20);
    float mean = g_mean[b], rstd = g_rstd[b];
    float4 v = *(const float4*)(g_virt + i4);
    float vv[4] = { v.x, v.y, v.z, v.w };
#pragma unroll
    for (int i = 0; i < 4; i++) {
        float y = fmaxf(fmaf((vv[i] - mean) * rstd, gamma[c + i], beta[c + i]), 0.f);
        __nv_bfloat16 h = __float2bfloat16(y);
        g_nh[i4 + i] = h;
        g_nl[i4 + i] = __float2bfloat16(y - __bfloat162float(h));
    }
}

// ================= launch =================
extern "C" void kernel_launch(void* const* d_in, const int* in_sizes, int n_in,
                              void* d_out, int out_size)
{
    const float* x     = (const float*)d_in[0];
    const float* Wq    = (const float*)d_in[1];
    const float* Wk    = (const float*)d_in[2];
    const float* Wv    = (const float*)d_in[3];
    const float* Wc    = (const float*)d_in[4];
    const float* Wout  = (const float*)d_in[5];
    const float* gamma = (const float*)d_in[6];
    const float* beta  = (const float*)d_in[7];
    float* out = (float*)d_out;

    cudaFuncSetAttribute(k_attn,    cudaFuncAttributeMaxDynamicSharedMemorySize, SM_ATTN_BYTES);
    cudaFuncSetAttribute(k_gemm<0>, cudaFuncAttributeMaxDynamicSharedMemorySize, SMEM_GEMM);
    cudaFuncSetAttribute(k_gemm<1>, cudaFuncAttributeMaxDynamicSharedMemorySize, SMEM_GEMM);

    k_zero<<<1, 128>>>();
    k_prep0<<<dim3(64, 4, 64), 256>>>(x);
    k_gmatA<<<16, 256>>>(Wq, Wk);
    k_gmatB<<<16, 256>>>(Wout, Wc);
    k_prepw<<<128, 256>>>(Wv, Wout);
    k_gemm<0><<<dim3(2048, 4), 256, SMEM_GEMM>>>(nullptr);   // z,v (bf16 split)
    k_attn<<<NL, 256, SM_ATTN_BYTES>>>();
    k_stats<<<1, 64>>>();
    k_prep2<<<65536, 256>>>(gamma, beta);
    k_gemm<1><<<dim3(2048, 2), 256, SMEM_GEMM>>>(out);       // out = Wout x + Wz gn
}